// round 4
// baseline (speedup 1.0000x reference)
#include <cuda_runtime.h>
#include <cuda_bf16.h>
#include <cstdint>

// SharedGroupLinearLayer via mma.sync bf16 (split hi/lo, 3 passes), 2 CTAs/SM.
// out = (x·W1^T + b1) + a0 * (x·(W0-W1)^T + (b0-b1)), a0 = sigmoid(x·(rw0-rw1))
// emb folded: (x+e)·W^T + b = x·W^T + EB[nb],  nb = token%16 (fixed per thread).
// Per tile: D[128 tok, 128] = X[128,64]·Wcat^T, Wcat=[W1;W0-W1], bf16 hi/lo x3.
// B fragments ldmatrix'd from SMEM per k-step (keeps regs <= 128 for occupancy 2).

#define THREADS 256
#define TILE_M  128
#define NTILES  2048
#define GRID    304

// dynamic smem offsets (base 1024-aligned)
#define ABUF_OFF 0         // 2 x 32KB: A tile bf16 (hi at +0, lo at +16384)
#define WH_OFF   65536     // 16KB Wcat hi
#define WL_OFF   81920     // 16KB Wcat lo
#define EB1_OFF  98304     // 16x64 f32: e·W1^T + b1
#define EBD_OFF  102400    // 16x64 f32: e·Wd^T + bd
#define GC_OFF   106496    // 16 f32: e·rwd
#define RWD_OFF  106560    // 64 f32
#define LOG_OFF  106816    // 2 x 128 f32 gate logits
#define SMEM_TOTAL 107840

__device__ __forceinline__ uint32_t smem_u32(const void* p) {
    uint32_t a;
    asm("{ .reg .u64 t; cvta.to.shared.u64 t, %1; cvt.u32.u64 %0, t; }" : "=r"(a) : "l"(p));
    return a;
}
// pack two f32 -> bf16x2 word: low 16 = first arg, high = second
__device__ __forceinline__ uint32_t cvt2bf(float lo, float hi) {
    uint32_t r;
    asm("cvt.rn.bf16x2.f32 %0, %1, %2;" : "=r"(r) : "f"(hi), "f"(lo));
    return r;
}
__device__ __forceinline__ void ldsm_x4(uint32_t* r, uint32_t addr) {
    asm volatile("ldmatrix.sync.aligned.m8n8.x4.shared.b16 {%0,%1,%2,%3}, [%4];"
        : "=r"(r[0]), "=r"(r[1]), "=r"(r[2]), "=r"(r[3]) : "r"(addr));
}
__device__ __forceinline__ void mma_bf16(float* d, const uint32_t* a, const uint32_t* b) {
    asm volatile("mma.sync.aligned.m16n8k16.row.col.f32.bf16.bf16.f32 "
        "{%0,%1,%2,%3}, {%4,%5,%6,%7}, {%8,%9}, {%0,%1,%2,%3};"
        : "+f"(d[0]), "+f"(d[1]), "+f"(d[2]), "+f"(d[3])
        : "r"(a[0]), "r"(a[1]), "r"(a[2]), "r"(a[3]), "r"(b[0]), "r"(b[1]));
}

__global__ __launch_bounds__(THREADS, 2)
void sgl_mma2_kernel(const float* __restrict__ x,
                     const float* __restrict__ emb,
                     const float* __restrict__ read_w,
                     const float* __restrict__ w_stack,
                     const float* __restrict__ b_stack,
                     float* __restrict__ out)
{
    extern __shared__ __align__(1024) char smem[];
    const uint32_t sb = smem_u32(smem);

    const int tid  = threadIdx.x;
    const int lane = tid & 31;
    const int wid  = tid >> 5;
    const int q    = wid & 3;      // n-column group (cols 16q..16q+15 of each half)
    const int r    = wid >> 2;     // m-half (tokens r*64 .. r*64+63)

    float* rwd_s = (float*)(smem + RWD_OFF);
    float* gc_s  = (float*)(smem + GC_OFF);
    float* eb1_s = (float*)(smem + EB1_OFF);
    float* ebd_s = (float*)(smem + EBD_OFF);
    float* log_s = (float*)(smem + LOG_OFF);

    // ---- one-time setup ----
    for (int i = tid; i < 64; i += THREADS)
        rwd_s[i] = read_w[2 * i] - read_w[2 * i + 1];

    // Wcat bf16 hi/lo: row n (128B = 64 bf16), XOR-swizzled 16B units
    for (int i = tid; i < 128 * 32; i += THREADS) {
        int n = i >> 5, kp = (i & 31) * 2;
        float v0, v1;
        if (n < 64) {
            v0 = w_stack[4096 + n * 64 + kp];
            v1 = w_stack[4096 + n * 64 + kp + 1];
        } else {
            int m = n - 64;
            v0 = w_stack[m * 64 + kp]     - w_stack[4096 + m * 64 + kp];
            v1 = w_stack[m * 64 + kp + 1] - w_stack[4096 + m * 64 + kp + 1];
        }
        uint32_t h = cvt2bf(v0, v1);
        float h0 = __uint_as_float(h << 16);
        float h1 = __uint_as_float(h & 0xffff0000u);
        uint32_t l = cvt2bf(v0 - h0, v1 - h1);
        int off = n * 128 + (((kp >> 3) ^ (n & 7)) << 4) + (kp & 7) * 2;
        *(uint32_t*)(smem + WH_OFF + off) = h;
        *(uint32_t*)(smem + WL_OFF + off) = l;
    }
    __syncthreads();   // rwd_s ready for gc below

    // EB tables: EB1[nb][o] = e[nb]·W1[o] + b1[o]; EBd[nb][o] = e[nb]·Wd[o] + bd[o]
    for (int i = tid; i < 16 * 64; i += THREADS) {
        int nb = i >> 6, o = i & 63;
        const float* ep  = emb + nb * 64;
        const float* w1p = w_stack + 4096 + o * 64;
        const float* w0p = w_stack + o * 64;
        float s1 = 0.f, s0 = 0.f;
        #pragma unroll 8
        for (int k = 0; k < 64; k++) { s1 += ep[k] * w1p[k]; s0 += ep[k] * w0p[k]; }
        float b1 = b_stack[64 + o];
        eb1_s[i] = s1 + b1;
        ebd_s[i] = (s0 - s1) + (b_stack[o] - b1);
    }
    if (tid < 16) {
        const float* ep = emb + tid * 64;
        float s = 0.f;
        #pragma unroll 8
        for (int k = 0; k < 64; k++) s += ep[k] * rwd_s[k];
        gc_s[tid] = s;
    }
    __syncthreads();

    // fixed per-thread indices
    const int cc   = tid & 15;        // convert chunk
    const int tnb  = tid >> 4;        // convert token % 16
    const int grp  = lane >> 2, tc = lane & 3;
    const float gcv = gc_s[tnb];
    const int alane = lane & 15;      // A ldsm row lane
    const int aunit = lane >> 4;      // A ldsm k-half

    // B ldsm addressing (x4: 2 n-tiles x 2 k-halves), rows fixed per lane
    const int brow_h1 = 16 * q + (lane & 7) + ((lane & 16) >> 1);        // rows 16q..16q+15
    const int brow_hd = 64 + brow_h1;                                     // +64
    const int bun     = (lane >> 3) & 1;                                  // k-half select

    for (int tile = blockIdx.x; tile < NTILES; tile += GRID)
    {
        const int buf = (tile / GRID) & 1;
        const uint32_t ab = sb + ABUF_OFF + buf * 32768;
        float* logb = log_s + buf * TILE_M;

        // ---- convert: LDG x -> gate partials + bf16 hi/lo STS ----
        {
            const float4* src = (const float4*)x + (size_t)tile * (TILE_M * 64 / 4);
            const float* rp = &rwd_s[cc * 4];
            float r0 = rp[0], r1 = rp[1], r2 = rp[2], r3 = rp[3];
            #pragma unroll
            for (int i = 0; i < 8; i++) {
                int j = tid + i * THREADS;
                int t = tnb + i * 16;
                float4 v = src[j];
                float p = v.x * r0 + v.y * r1 + v.z * r2 + v.w * r3;
                p += __shfl_xor_sync(0xffffffffu, p, 1);
                p += __shfl_xor_sync(0xffffffffu, p, 2);
                p += __shfl_xor_sync(0xffffffffu, p, 4);
                p += __shfl_xor_sync(0xffffffffu, p, 8);
                if ((lane & 15) == 0) logb[t] = p + gcv;
                uint32_t h0 = cvt2bf(v.x, v.y);
                uint32_t h1 = cvt2bf(v.z, v.w);
                float hx = __uint_as_float(h0 << 16), hy = __uint_as_float(h0 & 0xffff0000u);
                float hz = __uint_as_float(h1 << 16), hw = __uint_as_float(h1 & 0xffff0000u);
                uint32_t l0 = cvt2bf(v.x - hx, v.y - hy);
                uint32_t l1 = cvt2bf(v.z - hz, v.w - hw);
                uint32_t off = t * 128 + (((cc >> 1) ^ (t & 7)) << 4) + (cc & 1) * 8;
                *(uint2*)(smem + ABUF_OFF + buf * 32768 + off)         = make_uint2(h0, h1);
                *(uint2*)(smem + ABUF_OFF + buf * 32768 + off + 16384) = make_uint2(l0, l1);
            }
        }
        __syncthreads();

        // ---- MMA: 3 passes (xh·wh + xh·wl + xl·wh), B from SMEM per k ----
        float acc[4][4][4];
        #pragma unroll
        for (int m = 0; m < 4; m++)
            #pragma unroll
            for (int n = 0; n < 4; n++) {
                acc[m][n][0] = 0.f; acc[m][n][1] = 0.f;
                acc[m][n][2] = 0.f; acc[m][n][3] = 0.f;
            }

        #pragma unroll
        for (int k = 0; k < 4; k++) {
            uint32_t bh1h[4], bhdh[4], bh1l[4], bhdl[4];
            {
                uint32_t u  = (uint32_t)(k * 2 + bun);
                uint32_t a1 = sb + (uint32_t)(brow_h1 * 128) + (((u ^ (brow_h1 & 7))) << 4);
                uint32_t a2 = sb + (uint32_t)(brow_hd * 128) + (((u ^ (brow_hd & 7))) << 4);
                ldsm_x4(bh1h, a1 + WH_OFF);
                ldsm_x4(bhdh, a2 + WH_OFF);
                ldsm_x4(bh1l, a1 + WL_OFF);
                ldsm_x4(bhdl, a2 + WL_OFF);
            }
            #pragma unroll
            for (int m = 0; m < 4; m++) {
                int tok = r * 64 + m * 16 + alane;
                uint32_t un = (uint32_t)(k * 2 + aunit);
                uint32_t aaddr = ab + (uint32_t)(tok * 128) + ((un ^ (tok & 7)) << 4);
                uint32_t Ahi[4], Alo[4];
                ldsm_x4(Ahi, aaddr);
                ldsm_x4(Alo, aaddr + 16384);
                mma_bf16(acc[m][0], Ahi, &bh1h[0]);
                mma_bf16(acc[m][1], Ahi, &bh1h[2]);
                mma_bf16(acc[m][2], Ahi, &bhdh[0]);
                mma_bf16(acc[m][3], Ahi, &bhdh[2]);
                mma_bf16(acc[m][0], Ahi, &bh1l[0]);
                mma_bf16(acc[m][1], Ahi, &bh1l[2]);
                mma_bf16(acc[m][2], Ahi, &bhdl[0]);
                mma_bf16(acc[m][3], Ahi, &bhdl[2]);
                mma_bf16(acc[m][0], Alo, &bh1h[0]);
                mma_bf16(acc[m][1], Alo, &bh1h[2]);
                mma_bf16(acc[m][2], Alo, &bhdh[0]);
                mma_bf16(acc[m][3], Alo, &bhdh[2]);
            }
        }

        // ---- epilogue: EB fold + gate combine + direct STG ----
        {
            float* outb = out + (size_t)tile * (TILE_M * 64);
            const int nb0 = grp, nb1 = grp + 8;
            const int o0 = 16 * q + 2 * tc;       // np=0 cols
            const int o1 = o0 + 8;                // np=1 cols
            float2 e1a0 = *(const float2*)&eb1_s[nb0 * 64 + o0];
            float2 e1b0 = *(const float2*)&eb1_s[nb0 * 64 + o1];
            float2 eda0 = *(const float2*)&ebd_s[nb0 * 64 + o0];
            float2 edb0 = *(const float2*)&ebd_s[nb0 * 64 + o1];
            float2 e1a1 = *(const float2*)&eb1_s[nb1 * 64 + o0];
            float2 e1b1 = *(const float2*)&eb1_s[nb1 * 64 + o1];
            float2 eda1 = *(const float2*)&ebd_s[nb1 * 64 + o0];
            float2 edb1 = *(const float2*)&ebd_s[nb1 * 64 + o1];
            #pragma unroll
            for (int m = 0; m < 4; m++) {
                int t0 = r * 64 + m * 16 + grp;
                int t1 = t0 + 8;
                float a00 = 1.f / (1.f + __expf(-logb[t0]));
                float a01 = 1.f / (1.f + __expf(-logb[t1]));
                float2 w0, w1;
                // np = 0
                w0.x = fmaf(a00, acc[m][2][0] + eda0.x, acc[m][0][0] + e1a0.x);
                w0.y = fmaf(a00, acc[m][2][1] + eda0.y, acc[m][0][1] + e1a0.y);
                w1.x = fmaf(a01, acc[m][2][2] + eda1.x, acc[m][0][2] + e1a1.x);
                w1.y = fmaf(a01, acc[m][2][3] + eda1.y, acc[m][0][3] + e1a1.y);
                *(float2*)&outb[t0 * 64 + o0] = w0;
                *(float2*)&outb[t1 * 64 + o0] = w1;
                // np = 1
                w0.x = fmaf(a00, acc[m][3][0] + edb0.x, acc[m][1][0] + e1b0.x);
                w0.y = fmaf(a00, acc[m][3][1] + edb0.y, acc[m][1][1] + e1b0.y);
                w1.x = fmaf(a01, acc[m][3][2] + edb1.x, acc[m][1][2] + e1b1.x);
                w1.y = fmaf(a01, acc[m][3][3] + edb1.y, acc[m][1][3] + e1b1.y);
                *(float2*)&outb[t0 * 64 + o1] = w0;
                *(float2*)&outb[t1 * 64 + o1] = w1;
            }
        }
        // no trailing sync: next iter writes the other buffer; the per-iter
        // sync transitively protects reuse at distance 2.
    }
}

extern "C" void kernel_launch(void* const* d_in, const int* in_sizes, int n_in,
                              void* d_out, int out_size)
{
    const float* x       = (const float*)d_in[0];
    const float* emb     = (const float*)d_in[1];
    const float* read_w  = (const float*)d_in[2];
    const float* w_stack = (const float*)d_in[3];
    const float* b_stack = (const float*)d_in[4];
    float* out = (float*)d_out;

    cudaFuncSetAttribute(sgl_mma2_kernel, cudaFuncAttributeMaxDynamicSharedMemorySize, SMEM_TOTAL);
    sgl_mma2_kernel<<<GRID, THREADS, SMEM_TOTAL>>>(x, emb, read_w, w_stack, b_stack, out);
}

// round 5
// speedup vs baseline: 1.0005x; 1.0005x over previous
#include <cuda_runtime.h>
#include <cuda_bf16.h>
#include <cstdint>

// SharedGroupLinearLayer via mma.sync bf16 (split hi/lo, 3 passes), 2 CTAs/SM.
// out = (x·W1^T + b1) + a0 * (x·(W0-W1)^T + (b0-b1)), a0 = sigmoid(x·(rw0-rw1))
// emb folded: (x+e)·W^T + b = x·W^T + EB[nb],  nb = token%16 (fixed per thread).
// TILE_M=64 => 32 accumulators/thread so 2 CTAs/SM fit in 128 regs w/o spills.
// Per tile: D[64 tok, 128] = X[64,64]·Wcat^T, Wcat=[W1;W0-W1], bf16 hi/lo x3.

#define THREADS 256
#define TILE_M  64
#define NTILES  4096
#define GRID    304

// dynamic smem offsets (base 1024-aligned)
#define ABUF_OFF 0         // 2 x 16KB: A tile bf16 (hi at +0, lo at +8192)
#define WH_OFF   32768     // 16KB Wcat hi
#define WL_OFF   49152     // 16KB Wcat lo
#define EB1_OFF  65536     // 16x64 f32: e·W1^T + b1
#define EBD_OFF  69632     // 16x64 f32: e·Wd^T + bd
#define GC_OFF   73728     // 16 f32: e·rwd
#define RWD_OFF  73792     // 64 f32
#define LOG_OFF  74048     // 2 x 64 f32 gate logits
#define SMEM_TOTAL 74560

__device__ __forceinline__ uint32_t smem_u32(const void* p) {
    uint32_t a;
    asm("{ .reg .u64 t; cvta.to.shared.u64 t, %1; cvt.u32.u64 %0, t; }" : "=r"(a) : "l"(p));
    return a;
}
// pack two f32 -> bf16x2 word: low 16 = first arg, high = second
__device__ __forceinline__ uint32_t cvt2bf(float lo, float hi) {
    uint32_t r;
    asm("cvt.rn.bf16x2.f32 %0, %1, %2;" : "=r"(r) : "f"(hi), "f"(lo));
    return r;
}
__device__ __forceinline__ void ldsm_x4(uint32_t* r, uint32_t addr) {
    asm volatile("ldmatrix.sync.aligned.m8n8.x4.shared.b16 {%0,%1,%2,%3}, [%4];"
        : "=r"(r[0]), "=r"(r[1]), "=r"(r[2]), "=r"(r[3]) : "r"(addr));
}
__device__ __forceinline__ void mma_bf16(float* d, const uint32_t* a, const uint32_t* b) {
    asm volatile("mma.sync.aligned.m16n8k16.row.col.f32.bf16.bf16.f32 "
        "{%0,%1,%2,%3}, {%4,%5,%6,%7}, {%8,%9}, {%0,%1,%2,%3};"
        : "+f"(d[0]), "+f"(d[1]), "+f"(d[2]), "+f"(d[3])
        : "r"(a[0]), "r"(a[1]), "r"(a[2]), "r"(a[3]), "r"(b[0]), "r"(b[1]));
}

__global__ __launch_bounds__(THREADS, 2)
void sgl_mma3_kernel(const float* __restrict__ x,
                     const float* __restrict__ emb,
                     const float* __restrict__ read_w,
                     const float* __restrict__ w_stack,
                     const float* __restrict__ b_stack,
                     float* __restrict__ out)
{
    extern __shared__ __align__(1024) char smem[];
    const uint32_t sb = smem_u32(smem);

    const int tid  = threadIdx.x;
    const int lane = tid & 31;
    const int wid  = tid >> 5;
    const int q    = wid & 3;      // n-column group (cols 16q..16q+15 of each half)
    const int r    = wid >> 2;     // m-half (tokens r*32 .. r*32+31)

    float* rwd_s = (float*)(smem + RWD_OFF);
    float* gc_s  = (float*)(smem + GC_OFF);
    float* eb1_s = (float*)(smem + EB1_OFF);
    float* ebd_s = (float*)(smem + EBD_OFF);
    float* log_s = (float*)(smem + LOG_OFF);

    // ---- one-time setup ----
    for (int i = tid; i < 64; i += THREADS)
        rwd_s[i] = read_w[2 * i] - read_w[2 * i + 1];

    // Wcat bf16 hi/lo: row n (128B = 64 bf16), XOR-swizzled 16B units
    for (int i = tid; i < 128 * 32; i += THREADS) {
        int n = i >> 5, kp = (i & 31) * 2;
        float v0, v1;
        if (n < 64) {
            v0 = w_stack[4096 + n * 64 + kp];
            v1 = w_stack[4096 + n * 64 + kp + 1];
        } else {
            int m = n - 64;
            v0 = w_stack[m * 64 + kp]     - w_stack[4096 + m * 64 + kp];
            v1 = w_stack[m * 64 + kp + 1] - w_stack[4096 + m * 64 + kp + 1];
        }
        uint32_t h = cvt2bf(v0, v1);
        float h0 = __uint_as_float(h << 16);
        float h1 = __uint_as_float(h & 0xffff0000u);
        uint32_t l = cvt2bf(v0 - h0, v1 - h1);
        int off = n * 128 + (((kp >> 3) ^ (n & 7)) << 4) + (kp & 7) * 2;
        *(uint32_t*)(smem + WH_OFF + off) = h;
        *(uint32_t*)(smem + WL_OFF + off) = l;
    }
    __syncthreads();   // rwd_s ready for gc below

    // EB tables: EB1[nb][o] = e[nb]·W1[o] + b1[o]; EBd[nb][o] = e[nb]·Wd[o] + bd[o]
    for (int i = tid; i < 16 * 64; i += THREADS) {
        int nb = i >> 6, o = i & 63;
        const float* ep  = emb + nb * 64;
        const float* w1p = w_stack + 4096 + o * 64;
        const float* w0p = w_stack + o * 64;
        float s1 = 0.f, s0 = 0.f;
        #pragma unroll 8
        for (int k = 0; k < 64; k++) { s1 += ep[k] * w1p[k]; s0 += ep[k] * w0p[k]; }
        float b1 = b_stack[64 + o];
        eb1_s[i] = s1 + b1;
        ebd_s[i] = (s0 - s1) + (b_stack[o] - b1);
    }
    if (tid < 16) {
        const float* ep = emb + tid * 64;
        float s = 0.f;
        #pragma unroll 8
        for (int k = 0; k < 64; k++) s += ep[k] * rwd_s[k];
        gc_s[tid] = s;
    }
    __syncthreads();

    // fixed per-thread indices
    const int cc   = tid & 15;        // convert chunk
    const int tnb  = tid >> 4;        // convert token % 16 (token = tnb + 16i)
    const int grp  = lane >> 2, tc = lane & 3;
    const float gcv = gc_s[tnb];
    const int alane = lane & 15;      // A ldsm row lane
    const int aunit = lane >> 4;      // A ldsm k-half

    // B ldsm addressing (x4: 2 n-tiles x 2 k-halves), rows fixed per lane
    const int brow_h1 = 16 * q + (lane & 7) + ((lane & 16) >> 1);   // rows 16q..16q+15
    const int brow_hd = 64 + brow_h1;                                // +64
    const int bun     = (lane >> 3) & 1;                             // k-half select

    for (int tile = blockIdx.x; tile < NTILES; tile += GRID)
    {
        const int buf = (tile / GRID) & 1;
        const uint32_t ab = sb + ABUF_OFF + buf * 16384;
        float* logb = log_s + buf * TILE_M;

        // ---- convert: LDG x -> gate partials + bf16 hi/lo STS ----
        {
            const float4* src = (const float4*)x + (size_t)tile * (TILE_M * 64 / 4);
            const float* rp = &rwd_s[cc * 4];
            float r0 = rp[0], r1 = rp[1], r2 = rp[2], r3 = rp[3];
            #pragma unroll
            for (int i = 0; i < 4; i++) {
                int j = tid + i * THREADS;
                int t = tnb + i * 16;
                float4 v = src[j];
                float p = v.x * r0 + v.y * r1 + v.z * r2 + v.w * r3;
                p += __shfl_xor_sync(0xffffffffu, p, 1);
                p += __shfl_xor_sync(0xffffffffu, p, 2);
                p += __shfl_xor_sync(0xffffffffu, p, 4);
                p += __shfl_xor_sync(0xffffffffu, p, 8);
                if ((lane & 15) == 0) logb[t] = p + gcv;
                uint32_t h0 = cvt2bf(v.x, v.y);
                uint32_t h1 = cvt2bf(v.z, v.w);
                float hx = __uint_as_float(h0 << 16), hy = __uint_as_float(h0 & 0xffff0000u);
                float hz = __uint_as_float(h1 << 16), hw = __uint_as_float(h1 & 0xffff0000u);
                uint32_t l0 = cvt2bf(v.x - hx, v.y - hy);
                uint32_t l1 = cvt2bf(v.z - hz, v.w - hw);
                uint32_t off = (uint32_t)(t * 128 + (((cc >> 1) ^ (t & 7)) << 4) + (cc & 1) * 8);
                *(uint2*)(smem + ABUF_OFF + buf * 16384 + off)        = make_uint2(h0, h1);
                *(uint2*)(smem + ABUF_OFF + buf * 16384 + off + 8192) = make_uint2(l0, l1);
            }
        }
        __syncthreads();

        // ---- MMA: 3 passes (xh·wh + xh·wl + xl·wh), B from SMEM per k ----
        float acc[2][4][4];
        #pragma unroll
        for (int m = 0; m < 2; m++)
            #pragma unroll
            for (int n = 0; n < 4; n++) {
                acc[m][n][0] = 0.f; acc[m][n][1] = 0.f;
                acc[m][n][2] = 0.f; acc[m][n][3] = 0.f;
            }

        #pragma unroll
        for (int k = 0; k < 4; k++) {
            uint32_t bh1h[4], bhdh[4], bh1l[4], bhdl[4];
            {
                uint32_t u  = (uint32_t)(k * 2 + bun);
                uint32_t a1 = sb + (uint32_t)(brow_h1 * 128) + ((u ^ (brow_h1 & 7)) << 4);
                uint32_t a2 = sb + (uint32_t)(brow_hd * 128) + ((u ^ (brow_hd & 7)) << 4);
                ldsm_x4(bh1h, a1 + WH_OFF);
                ldsm_x4(bhdh, a2 + WH_OFF);
                ldsm_x4(bh1l, a1 + WL_OFF);
                ldsm_x4(bhdl, a2 + WL_OFF);
            }
            #pragma unroll
            for (int m = 0; m < 2; m++) {
                int tok = r * 32 + m * 16 + alane;
                uint32_t un = (uint32_t)(k * 2 + aunit);
                uint32_t aaddr = ab + (uint32_t)(tok * 128) + ((un ^ (tok & 7)) << 4);
                uint32_t Ahi[4], Alo[4];
                ldsm_x4(Ahi, aaddr);
                ldsm_x4(Alo, aaddr + 8192);
                mma_bf16(acc[m][0], Ahi, &bh1h[0]);
                mma_bf16(acc[m][1], Ahi, &bh1h[2]);
                mma_bf16(acc[m][2], Ahi, &bhdh[0]);
                mma_bf16(acc[m][3], Ahi, &bhdh[2]);
                mma_bf16(acc[m][0], Ahi, &bh1l[0]);
                mma_bf16(acc[m][1], Ahi, &bh1l[2]);
                mma_bf16(acc[m][2], Ahi, &bhdl[0]);
                mma_bf16(acc[m][3], Ahi, &bhdl[2]);
                mma_bf16(acc[m][0], Alo, &bh1h[0]);
                mma_bf16(acc[m][1], Alo, &bh1h[2]);
                mma_bf16(acc[m][2], Alo, &bhdh[0]);
                mma_bf16(acc[m][3], Alo, &bhdh[2]);
            }
        }

        // ---- epilogue: EB fold + gate combine + direct STG ----
        {
            float* outb = out + (size_t)tile * (TILE_M * 64);
            const int nb0 = grp, nb1 = grp + 8;     // token%16 for t0, t1
            const int o0 = 16 * q + 2 * tc;
            const int o1 = o0 + 8;
            #pragma unroll
            for (int m = 0; m < 2; m++) {
                int t0 = r * 32 + m * 16 + grp;
                int t1 = t0 + 8;
                float a00 = 1.f / (1.f + __expf(-logb[t0]));
                float a01 = 1.f / (1.f + __expf(-logb[t1]));
                float2 e1a0 = *(const float2*)&eb1_s[nb0 * 64 + o0];
                float2 eda0 = *(const float2*)&ebd_s[nb0 * 64 + o0];
                float2 e1a1 = *(const float2*)&eb1_s[nb1 * 64 + o0];
                float2 eda1 = *(const float2*)&ebd_s[nb1 * 64 + o0];
                float2 w0, w1;
                w0.x = fmaf(a00, acc[m][2][0] + eda0.x, acc[m][0][0] + e1a0.x);
                w0.y = fmaf(a00, acc[m][2][1] + eda0.y, acc[m][0][1] + e1a0.y);
                w1.x = fmaf(a01, acc[m][2][2] + eda1.x, acc[m][0][2] + e1a1.x);
                w1.y = fmaf(a01, acc[m][2][3] + eda1.y, acc[m][0][3] + e1a1.y);
                *(float2*)&outb[t0 * 64 + o0] = w0;
                *(float2*)&outb[t1 * 64 + o0] = w1;
                float2 e1b0 = *(const float2*)&eb1_s[nb0 * 64 + o1];
                float2 edb0 = *(const float2*)&ebd_s[nb0 * 64 + o1];
                float2 e1b1 = *(const float2*)&eb1_s[nb1 * 64 + o1];
                float2 edb1 = *(const float2*)&ebd_s[nb1 * 64 + o1];
                w0.x = fmaf(a00, acc[m][3][0] + edb0.x, acc[m][1][0] + e1b0.x);
                w0.y = fmaf(a00, acc[m][3][1] + edb0.y, acc[m][1][1] + e1b0.y);
                w1.x = fmaf(a01, acc[m][3][2] + edb1.x, acc[m][1][2] + e1b1.x);
                w1.y = fmaf(a01, acc[m][3][3] + edb1.y, acc[m][1][3] + e1b1.y);
                *(float2*)&outb[t0 * 64 + o1] = w0;
                *(float2*)&outb[t1 * 64 + o1] = w1;
            }
        }
        // no trailing sync: double buffer + the per-iter sync protects reuse
        // at distance 2 (all warps passed their own MMA before re-writing).
    }
}

extern "C" void kernel_launch(void* const* d_in, const int* in_sizes, int n_in,
                              void* d_out, int out_size)
{
    const float* x       = (const float*)d_in[0];
    const float* emb     = (const float*)d_in[1];
    const float* read_w  = (const float*)d_in[2];
    const float* w_stack = (const float*)d_in[3];
    const float* b_stack = (const float*)d_in[4];
    float* out = (float*)d_out;

    cudaFuncSetAttribute(sgl_mma3_kernel, cudaFuncAttributeMaxDynamicSharedMemorySize, SMEM_TOTAL);
    sgl_mma3_kernel<<<GRID, THREADS, SMEM_TOTAL>>>(x, emb, read_w, w_stack, b_stack, out);
}

// round 6
// speedup vs baseline: 3.0750x; 3.0735x over previous
#include <cuda_runtime.h>
#include <cuda_bf16.h>
#include <cstdint>

// SharedGroupLinearLayer via mma.sync bf16 (split hi/lo, 3 passes).
// out = (x·W1^T + b1) + a0 * (x·(W0-W1)^T + (b0-b1)), a0 = sigmoid(x·(rw0-rw1))
// R3 structure (B-fragments register-resident, TILE_M=128, 1 CTA/SM) plus
// cp.async double-buffered raw-x staging: tile i+1's x streams into SMEM
// during MMA/epilogue of tile i, removing LDG latency from the critical path.

#define THREADS 256
#define TILE_M  128
#define NTILES  2048
#define GRID    152

// dynamic smem offsets
#define RAW_OFF  0        // 2 x 32KB raw x (init: W hi at +0, W lo at +16384)
#define AB_OFF   65536    // 32KB bf16 A tile (hi +0, lo +16384)
#define EMB_OFF  98304    // 16x64 f32
#define RWD_OFF  102400   // 64 f32
#define B1_OFF   102656   // 64 f32
#define BD_OFF   102912   // 64 f32
#define LOG_OFF  103168   // 128 f32 gate logits
#define SMEM_TOTAL 103680

__device__ __forceinline__ uint32_t smem_u32(const void* p) {
    uint32_t a;
    asm("{ .reg .u64 t; cvta.to.shared.u64 t, %1; cvt.u32.u64 %0, t; }" : "=r"(a) : "l"(p));
    return a;
}
// pack two f32 -> bf16x2 word: low 16 = first arg, high = second
__device__ __forceinline__ uint32_t cvt2bf(float lo, float hi) {
    uint32_t r;
    asm("cvt.rn.bf16x2.f32 %0, %1, %2;" : "=r"(r) : "f"(hi), "f"(lo));
    return r;
}
__device__ __forceinline__ void ldsm_x4(uint32_t* r, uint32_t addr) {
    asm volatile("ldmatrix.sync.aligned.m8n8.x4.shared.b16 {%0,%1,%2,%3}, [%4];"
        : "=r"(r[0]), "=r"(r[1]), "=r"(r[2]), "=r"(r[3]) : "r"(addr));
}
__device__ __forceinline__ void ldsm_x2(uint32_t* r, uint32_t addr) {
    asm volatile("ldmatrix.sync.aligned.m8n8.x2.shared.b16 {%0,%1}, [%2];"
        : "=r"(r[0]), "=r"(r[1]) : "r"(addr));
}
__device__ __forceinline__ void mma_bf16(float* d, const uint32_t* a, const uint32_t* b) {
    asm volatile("mma.sync.aligned.m16n8k16.row.col.f32.bf16.bf16.f32 "
        "{%0,%1,%2,%3}, {%4,%5,%6,%7}, {%8,%9}, {%0,%1,%2,%3};"
        : "+f"(d[0]), "+f"(d[1]), "+f"(d[2]), "+f"(d[3])
        : "r"(a[0]), "r"(a[1]), "r"(a[2]), "r"(a[3]), "r"(b[0]), "r"(b[1]));
}
__device__ __forceinline__ void cp_async16(uint32_t daddr, const void* gptr) {
    asm volatile("cp.async.ca.shared.global [%0], [%1], 16;" :: "r"(daddr), "l"(gptr));
}
#define CP_COMMIT() asm volatile("cp.async.commit_group;" ::: "memory")
#define CP_WAIT1()  asm volatile("cp.async.wait_group 1;" ::: "memory")

__global__ __launch_bounds__(THREADS, 1)
void sgl_mma4_kernel(const float* __restrict__ x,
                     const float* __restrict__ emb,
                     const float* __restrict__ read_w,
                     const float* __restrict__ w_stack,
                     const float* __restrict__ b_stack,
                     float* __restrict__ out)
{
    extern __shared__ __align__(1024) char smem[];
    const uint32_t sb = smem_u32(smem);

    const int tid  = threadIdx.x;
    const int lane = tid & 31;
    const int wid  = tid >> 5;
    const int q    = wid & 3;      // n-column group
    const int r    = wid >> 2;     // m-half (tokens r*64..r*64+63)

    float* emb_s = (float*)(smem + EMB_OFF);
    float* rwd_s = (float*)(smem + RWD_OFF);
    float* b1_s  = (float*)(smem + B1_OFF);
    float* bd_s  = (float*)(smem + BD_OFF);
    float* log_s = (float*)(smem + LOG_OFF);

    // ---- one-time setup ----
    for (int i = tid; i < 64; i += THREADS) {
        rwd_s[i] = read_w[2 * i] - read_w[2 * i + 1];
        float b1 = b_stack[64 + i];
        b1_s[i] = b1;
        bd_s[i] = b_stack[i] - b1;
    }
    for (int i = tid; i < 16 * 64; i += THREADS) emb_s[i] = emb[i];

    // Wcat bf16 hi/lo into RAW area (temporarily): row n = 128B, XOR swizzle
    for (int i = tid; i < 128 * 32; i += THREADS) {
        int n = i >> 5, kp = (i & 31) * 2;
        float v0, v1;
        if (n < 64) {
            v0 = w_stack[4096 + n * 64 + kp];
            v1 = w_stack[4096 + n * 64 + kp + 1];
        } else {
            int m = n - 64;
            v0 = w_stack[m * 64 + kp]     - w_stack[4096 + m * 64 + kp];
            v1 = w_stack[m * 64 + kp + 1] - w_stack[4096 + m * 64 + kp + 1];
        }
        uint32_t h = cvt2bf(v0, v1);
        float h0 = __uint_as_float(h << 16);
        float h1 = __uint_as_float(h & 0xffff0000u);
        uint32_t l = cvt2bf(v0 - h0, v1 - h1);
        int off = n * 128 + (((kp >> 3) ^ (n & 7)) << 4) + (kp & 7) * 2;
        *(uint32_t*)(smem + RAW_OFF + off)         = h;
        *(uint32_t*)(smem + RAW_OFF + 16384 + off) = l;
    }
    __syncthreads();

    // ---- B fragments -> registers (kept for whole kernel) ----
    // warp q owns n8-tiles {2q, 2q+1, 2q+8, 2q+9}; nti 0,1 = h1 cols, 2,3 = hd
    uint32_t Bh[4][4][2], Bl[4][4][2];
    #pragma unroll
    for (int nti = 0; nti < 4; nti++) {
        int nt = 2 * q + (nti & 1) + ((nti >> 1) << 3);
        #pragma unroll
        for (int k = 0; k < 4; k++) {
            int row  = nt * 8 + (lane & 7);
            int unit = k * 2 + ((lane >> 3) & 1);
            uint32_t addr = sb + RAW_OFF + row * 128 + ((unit ^ (row & 7)) << 4);
            ldsm_x2(Bh[nti][k], addr);
            ldsm_x2(Bl[nti][k], addr + 16384);
        }
    }
    __syncthreads();   // RAW area now free for x staging

    const int grp = lane >> 2, tc = lane & 3;

    // ---- prologue: stage first tile's x ----
    {
        int tile0 = blockIdx.x;
        const float4* src = (const float4*)x + (size_t)tile0 * (TILE_M * 64 / 4);
        #pragma unroll
        for (int k = 0; k < 8; k++) {
            int j = tid + k * THREADS;
            cp_async16(sb + RAW_OFF + j * 16, src + j);
        }
    }
    CP_COMMIT();

    int buf = 0;
    for (int tile = blockIdx.x; tile < NTILES; tile += GRID)
    {
        // ---- prefetch next tile into other raw buffer ----
        {
            int nt = tile + GRID;
            if (nt < NTILES) {
                const float4* src = (const float4*)x + (size_t)nt * (TILE_M * 64 / 4);
                uint32_t dst = sb + RAW_OFF + (buf ^ 1) * 32768;
                #pragma unroll
                for (int k = 0; k < 8; k++) {
                    int j = tid + k * THREADS;
                    cp_async16(dst + j * 16, src + j);
                }
            }
        }
        CP_COMMIT();
        CP_WAIT1();          // current tile's copy complete
        __syncthreads();     // visibility + separates prev MMA from A-tile rewrite

        // ---- convert: LDS raw -> gate partials + bf16 hi/lo STS ----
        {
            const float4* raw4 = (const float4*)(smem + RAW_OFF + buf * 32768);
            #pragma unroll
            for (int i = 0; i < 8; i++) {
                int j = tid + i * THREADS;
                int t = j >> 4, c = j & 15;      // token, chunk (k = 4c..4c+3)
                float4 v = raw4[j];
                const float* ep = &emb_s[(t & 15) * 64 + c * 4];
                v.x += ep[0]; v.y += ep[1]; v.z += ep[2]; v.w += ep[3];
                const float* rp = &rwd_s[c * 4];
                float p = v.x * rp[0] + v.y * rp[1] + v.z * rp[2] + v.w * rp[3];
                p += __shfl_xor_sync(0xffffffffu, p, 1);
                p += __shfl_xor_sync(0xffffffffu, p, 2);
                p += __shfl_xor_sync(0xffffffffu, p, 4);
                p += __shfl_xor_sync(0xffffffffu, p, 8);
                if ((lane & 15) == 0) log_s[t] = p;
                uint32_t h0 = cvt2bf(v.x, v.y);
                uint32_t h1 = cvt2bf(v.z, v.w);
                float hx = __uint_as_float(h0 << 16), hy = __uint_as_float(h0 & 0xffff0000u);
                float hz = __uint_as_float(h1 << 16), hw = __uint_as_float(h1 & 0xffff0000u);
                uint32_t l0 = cvt2bf(v.x - hx, v.y - hy);
                uint32_t l1 = cvt2bf(v.z - hz, v.w - hw);
                int off = t * 128 + (((c >> 1) ^ (t & 7)) << 4) + (c & 1) * 8;
                *(uint2*)(smem + AB_OFF + off)         = make_uint2(h0, h1);
                *(uint2*)(smem + AB_OFF + off + 16384) = make_uint2(l0, l1);
            }
        }
        __syncthreads();

        // ---- MMA: 3 passes (xh·wh + xh·wl + xl·wh), B in registers ----
        float acc[4][4][4];
        #pragma unroll
        for (int m = 0; m < 4; m++)
            #pragma unroll
            for (int n = 0; n < 4; n++) {
                acc[m][n][0] = 0.f; acc[m][n][1] = 0.f;
                acc[m][n][2] = 0.f; acc[m][n][3] = 0.f;
            }

        #pragma unroll
        for (int k = 0; k < 4; k++) {
            #pragma unroll
            for (int m = 0; m < 4; m++) {
                int tok  = r * 64 + m * 16 + (lane & 15);
                int unit = k * 2 + (lane >> 4);
                uint32_t aaddr = sb + AB_OFF + tok * 128 + ((unit ^ (tok & 7)) << 4);
                uint32_t Ahi[4], Alo[4];
                ldsm_x4(Ahi, aaddr);
                ldsm_x4(Alo, aaddr + 16384);
                #pragma unroll
                for (int n = 0; n < 4; n++) mma_bf16(acc[m][n], Ahi, Bh[n][k]);
                #pragma unroll
                for (int n = 0; n < 4; n++) mma_bf16(acc[m][n], Ahi, Bl[n][k]);
                #pragma unroll
                for (int n = 0; n < 4; n++) mma_bf16(acc[m][n], Alo, Bh[n][k]);
            }
        }

        // ---- epilogue: gate combine + direct STG ----
        {
            float* outb = out + (size_t)tile * (TILE_M * 64);
            #pragma unroll
            for (int m = 0; m < 4; m++) {
                int t0 = r * 64 + m * 16 + grp;
                int t1 = t0 + 8;
                float a00 = 1.f / (1.f + __expf(-log_s[t0]));
                float a01 = 1.f / (1.f + __expf(-log_s[t1]));
                #pragma unroll
                for (int np = 0; np < 2; np++) {
                    int o = (2 * q + np) * 8 + tc * 2;
                    float2 b1v = *(const float2*)&b1_s[o];
                    float2 bdv = *(const float2*)&bd_s[o];
                    const float* h1p = acc[m][np];
                    const float* hdp = acc[m][np + 2];
                    float2 r0, r1;
                    r0.x = fmaf(a00, hdp[0] + bdv.x, h1p[0] + b1v.x);
                    r0.y = fmaf(a00, hdp[1] + bdv.y, h1p[1] + b1v.y);
                    r1.x = fmaf(a01, hdp[2] + bdv.x, h1p[2] + b1v.x);
                    r1.y = fmaf(a01, hdp[3] + bdv.y, h1p[3] + b1v.y);
                    *(float2*)&outb[t0 * 64 + o] = r0;
                    *(float2*)&outb[t1 * 64 + o] = r1;
                }
            }
        }
        buf ^= 1;
        // no trailing sync: the wait+sync at the top of the next iteration
        // separates this MMA/epilogue from the next A-tile rewrite.
    }
}

extern "C" void kernel_launch(void* const* d_in, const int* in_sizes, int n_in,
                              void* d_out, int out_size)
{
    const float* x       = (const float*)d_in[0];
    const float* emb     = (const float*)d_in[1];
    const float* read_w  = (const float*)d_in[2];
    const float* w_stack = (const float*)d_in[3];
    const float* b_stack = (const float*)d_in[4];
    float* out = (float*)d_out;

    cudaFuncSetAttribute(sgl_mma4_kernel, cudaFuncAttributeMaxDynamicSharedMemorySize, SMEM_TOTAL);
    sgl_mma4_kernel<<<GRID, THREADS, SMEM_TOTAL>>>(x, emb, read_w, w_stack, b_stack, out);
}

// round 7
// speedup vs baseline: 3.0905x; 1.0050x over previous
#include <cuda_runtime.h>
#include <cuda_bf16.h>
#include <cstdint>

// SharedGroupLinearLayer via mma.sync bf16 (split hi/lo, 3 passes).
// out = (x·W1^T + b1) + a0 * (x·(W0-W1)^T + (b0-b1)), a0 = sigmoid(x·(rw0-rw1))
// Round 7: single barrier per tile; convert(i+1) is interleaved into the
// MMA(i) instruction stream (A-tile double buffered, so no hazard), letting
// LSU/FMA convert work execute under tensor-pipe MMA time. B columns are
// permuted at build time so the epilogue stores 4 contiguous floats (STG.128).

#define THREADS 256
#define TILE_M  128
#define NTILES  2048
#define GRID    152

// dynamic smem offsets
#define RAW_OFF  0        // 2 x 32KB raw x
#define AB_OFF   65536    // 2 x 32KB bf16 A tile (hi +0, lo +16384); init: W tiles
#define EMB_OFF  131072   // 16x64 f32
#define RWD_OFF  135168   // 64 f32
#define B1_OFF   135424   // 64 f32
#define BD_OFF   135680   // 64 f32
#define LOG_OFF  135936   // 2 x 128 f32 gate logits
#define SMEM_TOTAL 136960

__device__ __forceinline__ uint32_t smem_u32(const void* p) {
    uint32_t a;
    asm("{ .reg .u64 t; cvta.to.shared.u64 t, %1; cvt.u32.u64 %0, t; }" : "=r"(a) : "l"(p));
    return a;
}
// pack two f32 -> bf16x2 word: low 16 = first arg, high = second
__device__ __forceinline__ uint32_t cvt2bf(float lo, float hi) {
    uint32_t r;
    asm("cvt.rn.bf16x2.f32 %0, %1, %2;" : "=r"(r) : "f"(hi), "f"(lo));
    return r;
}
__device__ __forceinline__ void ldsm_x4(uint32_t* r, uint32_t addr) {
    asm volatile("ldmatrix.sync.aligned.m8n8.x4.shared.b16 {%0,%1,%2,%3}, [%4];"
        : "=r"(r[0]), "=r"(r[1]), "=r"(r[2]), "=r"(r[3]) : "r"(addr));
}
__device__ __forceinline__ void ldsm_x2(uint32_t* r, uint32_t addr) {
    asm volatile("ldmatrix.sync.aligned.m8n8.x2.shared.b16 {%0,%1}, [%2];"
        : "=r"(r[0]), "=r"(r[1]) : "r"(addr));
}
__device__ __forceinline__ void mma_bf16(float* d, const uint32_t* a, const uint32_t* b) {
    asm volatile("mma.sync.aligned.m16n8k16.row.col.f32.bf16.bf16.f32 "
        "{%0,%1,%2,%3}, {%4,%5,%6,%7}, {%8,%9}, {%0,%1,%2,%3};"
        : "+f"(d[0]), "+f"(d[1]), "+f"(d[2]), "+f"(d[3])
        : "r"(a[0]), "r"(a[1]), "r"(a[2]), "r"(a[3]), "r"(b[0]), "r"(b[1]));
}
__device__ __forceinline__ void cp_async16(uint32_t daddr, const void* gptr) {
    asm volatile("cp.async.ca.shared.global [%0], [%1], 16;" :: "r"(daddr), "l"(gptr));
}
#define CP_COMMIT() asm volatile("cp.async.commit_group;" ::: "memory")
#define CP_WAIT0()  asm volatile("cp.async.wait_group 0;" ::: "memory")
#define CP_WAIT1()  asm volatile("cp.async.wait_group 1;" ::: "memory")

__global__ __launch_bounds__(THREADS, 1)
void sgl_mma5_kernel(const float* __restrict__ x,
                     const float* __restrict__ emb,
                     const float* __restrict__ read_w,
                     const float* __restrict__ w_stack,
                     const float* __restrict__ b_stack,
                     float* __restrict__ out)
{
    extern __shared__ __align__(1024) char smem[];
    const uint32_t sb = smem_u32(smem);

    const int tid  = threadIdx.x;
    const int lane = tid & 31;
    const int wid  = tid >> 5;
    const int q    = wid & 3;      // n-column group
    const int r    = wid >> 2;     // m-half (tokens r*64..r*64+63)

    float* emb_s = (float*)(smem + EMB_OFF);
    float* rwd_s = (float*)(smem + RWD_OFF);
    float* b1_s  = (float*)(smem + B1_OFF);
    float* bd_s  = (float*)(smem + BD_OFF);
    float* log_s = (float*)(smem + LOG_OFF);

    // ---- one-time setup ----
    for (int i = tid; i < 64; i += THREADS) {
        rwd_s[i] = read_w[2 * i] - read_w[2 * i + 1];
        float b1 = b_stack[64 + i];
        b1_s[i] = b1;
        bd_s[i] = b_stack[i] - b1;
    }
    for (int i = tid; i < 16 * 64; i += THREADS) emb_s[i] = emb[i];

    // Wcat bf16 hi/lo into AB area (temporarily), with COLUMN PERMUTATION:
    // smem row n (mma column) <- weight output-col o so that thread (q,tc)
    // ends up owning 4 contiguous outputs 16q+4tc..16q+4tc+3.
    for (int i = tid; i < 128 * 32; i += THREADS) {
        int n = i >> 5, kp = (i & 31) * 2;
        int half = n >> 6;              // 0: W1, 1: W0-W1
        int nn = n & 63;
        int p = nn & 7, t = (nn >> 3) & 1;
        int o = (nn & 48) + ((p >> 1) << 2) + 2 * t + (p & 1);
        float v0, v1;
        if (half == 0) {
            v0 = w_stack[4096 + o * 64 + kp];
            v1 = w_stack[4096 + o * 64 + kp + 1];
        } else {
            v0 = w_stack[o * 64 + kp]     - w_stack[4096 + o * 64 + kp];
            v1 = w_stack[o * 64 + kp + 1] - w_stack[4096 + o * 64 + kp + 1];
        }
        uint32_t h = cvt2bf(v0, v1);
        float h0 = __uint_as_float(h << 16);
        float h1 = __uint_as_float(h & 0xffff0000u);
        uint32_t l = cvt2bf(v0 - h0, v1 - h1);
        int off = n * 128 + (((kp >> 3) ^ (n & 7)) << 4) + (kp & 7) * 2;
        *(uint32_t*)(smem + AB_OFF + off)         = h;
        *(uint32_t*)(smem + AB_OFF + 16384 + off) = l;
    }
    __syncthreads();

    // ---- B fragments -> registers (kept for whole kernel) ----
    uint32_t Bh[4][4][2], Bl[4][4][2];
    #pragma unroll
    for (int nti = 0; nti < 4; nti++) {
        int nt = 2 * q + (nti & 1) + ((nti >> 1) << 3);
        #pragma unroll
        for (int k = 0; k < 4; k++) {
            int row  = nt * 8 + (lane & 7);
            int unit = k * 2 + ((lane >> 3) & 1);
            uint32_t addr = sb + AB_OFF + row * 128 + ((unit ^ (row & 7)) << 4);
            ldsm_x2(Bh[nti][k], addr);
            ldsm_x2(Bl[nti][k], addr + 16384);
        }
    }
    __syncthreads();   // AB area now free for A tiles

    const int grp = lane >> 2, tc = lane & 3;
    const int o0  = 16 * q + 4 * tc;

    // ---- prologue: stage + convert first tile ----
    {
        const float4* src = (const float4*)x + (size_t)blockIdx.x * (TILE_M * 64 / 4);
        #pragma unroll
        for (int k = 0; k < 8; k++) {
            int j = tid + k * THREADS;
            cp_async16(sb + RAW_OFF + j * 16, src + j);
        }
    }
    CP_COMMIT();
    CP_WAIT0();
    // convert tile0: raw[0] -> A[0], log[0]
    {
        const float4* raw4 = (const float4*)(smem + RAW_OFF);
        #pragma unroll
        for (int i = 0; i < 8; i++) {
            int j = tid + i * THREADS;
            int t = j >> 4, c = j & 15;
            float4 v = raw4[j];
            const float* ep = &emb_s[(t & 15) * 64 + c * 4];
            v.x += ep[0]; v.y += ep[1]; v.z += ep[2]; v.w += ep[3];
            const float* rp = &rwd_s[c * 4];
            float p = v.x * rp[0] + v.y * rp[1] + v.z * rp[2] + v.w * rp[3];
            p += __shfl_xor_sync(0xffffffffu, p, 1);
            p += __shfl_xor_sync(0xffffffffu, p, 2);
            p += __shfl_xor_sync(0xffffffffu, p, 4);
            p += __shfl_xor_sync(0xffffffffu, p, 8);
            if ((lane & 15) == 0) log_s[t] = p;
            uint32_t h0 = cvt2bf(v.x, v.y);
            uint32_t h1 = cvt2bf(v.z, v.w);
            float hx = __uint_as_float(h0 << 16), hy = __uint_as_float(h0 & 0xffff0000u);
            float hz = __uint_as_float(h1 << 16), hw = __uint_as_float(h1 & 0xffff0000u);
            uint32_t l0 = cvt2bf(v.x - hx, v.y - hy);
            uint32_t l1 = cvt2bf(v.z - hz, v.w - hw);
            int off = t * 128 + (((c >> 1) ^ (t & 7)) << 4) + (c & 1) * 8;
            *(uint2*)(smem + AB_OFF + off)         = make_uint2(h0, h1);
            *(uint2*)(smem + AB_OFF + off + 16384) = make_uint2(l0, l1);
        }
    }
    // stage tile0+GRID into raw[1]
    {
        int nt = blockIdx.x + GRID;
        if (nt < NTILES) {
            const float4* src = (const float4*)x + (size_t)nt * (TILE_M * 64 / 4);
            #pragma unroll
            for (int k = 0; k < 8; k++) {
                int j = tid + k * THREADS;
                cp_async16(sb + RAW_OFF + 32768 + j * 16, src + j);
            }
        }
    }
    CP_COMMIT();

    int b = 0, rb = 1;
    for (int tile = blockIdx.x; tile < NTILES; tile += GRID)
    {
        __syncthreads();   // A[b], log[b] visible; prior reads of A[b^1] done

        // prefetch tile+2*GRID into raw[rb^1]
        {
            int nt2 = tile + 2 * GRID;
            if (nt2 < NTILES) {
                const float4* src = (const float4*)x + (size_t)nt2 * (TILE_M * 64 / 4);
                uint32_t dst = sb + RAW_OFF + (rb ^ 1) * 32768;
                #pragma unroll
                for (int k = 0; k < 8; k++) {
                    int j = tid + k * THREADS;
                    cp_async16(dst + j * 16, src + j);
                }
            }
        }
        CP_COMMIT();
        CP_WAIT1();   // raw[rb] (tile+GRID) ready (same-thread consumption)

        const bool hasnext = (tile + GRID) < NTILES;
        const uint32_t abR = sb + AB_OFF + b * 32768;          // MMA source
        const uint32_t abW = sb + AB_OFF + (b ^ 1) * 32768;    // convert dest
        const float4* raw4 = (const float4*)(smem + RAW_OFF + rb * 32768);
        float* logW = log_s + (b ^ 1) * TILE_M;
        float* logR = log_s + b * TILE_M;

        float acc[4][4][4];
        #pragma unroll
        for (int m = 0; m < 4; m++)
            #pragma unroll
            for (int n = 0; n < 4; n++) {
                acc[m][n][0] = 0.f; acc[m][n][1] = 0.f;
                acc[m][n][2] = 0.f; acc[m][n][3] = 0.f;
            }

        // ---- fused: 16 MMA groups with 8 convert chunks woven between ----
        #pragma unroll
        for (int km = 0; km < 16; km++) {
            const int k = km >> 2, m = km & 3;
            {
                int tok  = r * 64 + m * 16 + (lane & 15);
                int unit = k * 2 + (lane >> 4);
                uint32_t aaddr = abR + tok * 128 + ((unit ^ (tok & 7)) << 4);
                uint32_t Ahi[4], Alo[4];
                ldsm_x4(Ahi, aaddr);
                ldsm_x4(Alo, aaddr + 16384);
                #pragma unroll
                for (int n = 0; n < 4; n++) mma_bf16(acc[m][n], Ahi, Bh[n][k]);
                #pragma unroll
                for (int n = 0; n < 4; n++) mma_bf16(acc[m][n], Ahi, Bl[n][k]);
                #pragma unroll
                for (int n = 0; n < 4; n++) mma_bf16(acc[m][n], Alo, Bh[n][k]);
            }
            if (km < 8 && hasnext) {
                const int i = km;
                int j = tid + i * THREADS;
                int t = j >> 4, c = j & 15;
                float4 v = raw4[j];
                const float* ep = &emb_s[(t & 15) * 64 + c * 4];
                v.x += ep[0]; v.y += ep[1]; v.z += ep[2]; v.w += ep[3];
                const float* rp = &rwd_s[c * 4];
                float p = v.x * rp[0] + v.y * rp[1] + v.z * rp[2] + v.w * rp[3];
                p += __shfl_xor_sync(0xffffffffu, p, 1);
                p += __shfl_xor_sync(0xffffffffu, p, 2);
                p += __shfl_xor_sync(0xffffffffu, p, 4);
                p += __shfl_xor_sync(0xffffffffu, p, 8);
                if ((lane & 15) == 0) logW[t] = p;
                uint32_t h0 = cvt2bf(v.x, v.y);
                uint32_t h1 = cvt2bf(v.z, v.w);
                float hx = __uint_as_float(h0 << 16), hy = __uint_as_float(h0 & 0xffff0000u);
                float hz = __uint_as_float(h1 << 16), hw = __uint_as_float(h1 & 0xffff0000u);
                uint32_t l0 = cvt2bf(v.x - hx, v.y - hy);
                uint32_t l1 = cvt2bf(v.z - hz, v.w - hw);
                int off = t * 128 + (((c >> 1) ^ (t & 7)) << 4) + (c & 1) * 8;
                *(uint2*)(smem + AB_OFF + (b ^ 1) * 32768 + off)         = make_uint2(h0, h1);
                *(uint2*)(smem + AB_OFF + (b ^ 1) * 32768 + off + 16384) = make_uint2(l0, l1);
            }
        }
        (void)abW;

        // ---- epilogue: gate combine + STG.128 (permuted-contiguous cols) ----
        {
            float* outb = out + (size_t)tile * (TILE_M * 64);
            float4 b1v = *(const float4*)&b1_s[o0];
            float4 bdv = *(const float4*)&bd_s[o0];
            #pragma unroll
            for (int m = 0; m < 4; m++) {
                int t0 = r * 64 + m * 16 + grp;
                int t1 = t0 + 8;
                float a00 = 1.f / (1.f + __expf(-logR[t0]));
                float a01 = 1.f / (1.f + __expf(-logR[t1]));
                float4 w;
                w.x = fmaf(a00, acc[m][2][0] + bdv.x, acc[m][0][0] + b1v.x);
                w.y = fmaf(a00, acc[m][2][1] + bdv.y, acc[m][0][1] + b1v.y);
                w.z = fmaf(a00, acc[m][3][0] + bdv.z, acc[m][1][0] + b1v.z);
                w.w = fmaf(a00, acc[m][3][1] + bdv.w, acc[m][1][1] + b1v.w);
                *(float4*)&outb[t0 * 64 + o0] = w;
                w.x = fmaf(a01, acc[m][2][2] + bdv.x, acc[m][0][2] + b1v.x);
                w.y = fmaf(a01, acc[m][2][3] + bdv.y, acc[m][0][3] + b1v.y);
                w.z = fmaf(a01, acc[m][3][2] + bdv.z, acc[m][1][2] + b1v.z);
                w.w = fmaf(a01, acc[m][3][3] + bdv.w, acc[m][1][3] + b1v.w);
                *(float4*)&outb[t1 * 64 + o0] = w;
            }
        }
        b ^= 1; rb ^= 1;
    }
}

extern "C" void kernel_launch(void* const* d_in, const int* in_sizes, int n_in,
                              void* d_out, int out_size)
{
    const float* x       = (const float*)d_in[0];
    const float* emb     = (const float*)d_in[1];
    const float* read_w  = (const float*)d_in[2];
    const float* w_stack = (const float*)d_in[3];
    const float* b_stack = (const float*)d_in[4];
    float* out = (float*)d_out;

    cudaFuncSetAttribute(sgl_mma5_kernel, cudaFuncAttributeMaxDynamicSharedMemorySize, SMEM_TOTAL);
    sgl_mma5_kernel<<<GRID, THREADS, SMEM_TOTAL>>>(x, emb, read_w, w_stack, b_stack, out);
}

// round 8
// speedup vs baseline: 3.6629x; 1.1852x over previous
#include <cuda_runtime.h>
#include <cuda_bf16.h>
#include <cstdint>

// SharedGroupLinearLayer via mma.sync bf16 (split hi/lo, 3 passes), 2 CTAs/SM.
// out = (x·W1^T + b1) + a0 * (x·(W0-W1)^T + (b0-b1)), a0 = sigmoid(x·(rw0-rw1))
// Round 8: 16 warps/SM. TILE_M=64 (acc 32 regs), B-hi fragments in registers
// (32 regs), B-lo ldmatrix'd from SMEM per k-step. Fits 128 regs => occupancy 2.
// Column-permuted W so each thread stores 4 contiguous outputs (STG.128).

#define THREADS 256
#define TILE_M  64
#define NTILES  4096
#define GRID    304

// dynamic smem offsets
#define RAW_OFF  0        // 2 x 16KB raw x
#define AB_OFF   32768    // 16KB bf16 A tile (hi +0, lo +8192); init: Wcat hi
#define WLO_OFF  49152    // 16KB Wcat lo (persistent)
#define EMB_OFF  65536    // 16x64 f32
#define RWD_OFF  69632    // 64 f32
#define B1_OFF   69888    // 64 f32
#define BD_OFF   70144    // 64 f32
#define LOG_OFF  70400    // 64 f32 gate logits
#define SMEM_TOTAL 70656

__device__ __forceinline__ uint32_t smem_u32(const void* p) {
    uint32_t a;
    asm("{ .reg .u64 t; cvta.to.shared.u64 t, %1; cvt.u32.u64 %0, t; }" : "=r"(a) : "l"(p));
    return a;
}
// pack two f32 -> bf16x2 word: low 16 = first arg, high = second
__device__ __forceinline__ uint32_t cvt2bf(float lo, float hi) {
    uint32_t r;
    asm("cvt.rn.bf16x2.f32 %0, %1, %2;" : "=r"(r) : "f"(hi), "f"(lo));
    return r;
}
__device__ __forceinline__ void ldsm_x4(uint32_t* r, uint32_t addr) {
    asm volatile("ldmatrix.sync.aligned.m8n8.x4.shared.b16 {%0,%1,%2,%3}, [%4];"
        : "=r"(r[0]), "=r"(r[1]), "=r"(r[2]), "=r"(r[3]) : "r"(addr));
}
__device__ __forceinline__ void ldsm_x2(uint32_t* r, uint32_t addr) {
    asm volatile("ldmatrix.sync.aligned.m8n8.x2.shared.b16 {%0,%1}, [%2];"
        : "=r"(r[0]), "=r"(r[1]) : "r"(addr));
}
__device__ __forceinline__ void mma_bf16(float* d, const uint32_t* a, const uint32_t* b) {
    asm volatile("mma.sync.aligned.m16n8k16.row.col.f32.bf16.bf16.f32 "
        "{%0,%1,%2,%3}, {%4,%5,%6,%7}, {%8,%9}, {%0,%1,%2,%3};"
        : "+f"(d[0]), "+f"(d[1]), "+f"(d[2]), "+f"(d[3])
        : "r"(a[0]), "r"(a[1]), "r"(a[2]), "r"(a[3]), "r"(b[0]), "r"(b[1]));
}
__device__ __forceinline__ void cp_async16(uint32_t daddr, const void* gptr) {
    asm volatile("cp.async.ca.shared.global [%0], [%1], 16;" :: "r"(daddr), "l"(gptr));
}
#define CP_COMMIT() asm volatile("cp.async.commit_group;" ::: "memory")
#define CP_WAIT1()  asm volatile("cp.async.wait_group 1;" ::: "memory")

__global__ __launch_bounds__(THREADS, 2)
void sgl_mma6_kernel(const float* __restrict__ x,
                     const float* __restrict__ emb,
                     const float* __restrict__ read_w,
                     const float* __restrict__ w_stack,
                     const float* __restrict__ b_stack,
                     float* __restrict__ out)
{
    extern __shared__ __align__(1024) char smem[];
    const uint32_t sb = smem_u32(smem);

    const int tid  = threadIdx.x;
    const int lane = tid & 31;
    const int wid  = tid >> 5;
    const int q    = wid & 3;      // n-column group (cols 16q..16q+15 of each half)
    const int r    = wid >> 2;     // m-half (tokens r*32..r*32+31)

    float* emb_s = (float*)(smem + EMB_OFF);
    float* rwd_s = (float*)(smem + RWD_OFF);
    float* b1_s  = (float*)(smem + B1_OFF);
    float* bd_s  = (float*)(smem + BD_OFF);
    float* log_s = (float*)(smem + LOG_OFF);

    // ---- one-time setup ----
    for (int i = tid; i < 64; i += THREADS) {
        rwd_s[i] = read_w[2 * i] - read_w[2 * i + 1];
        float b1 = b_stack[64 + i];
        b1_s[i] = b1;
        bd_s[i] = b_stack[i] - b1;
    }
    for (int i = tid; i < 16 * 64; i += THREADS) emb_s[i] = emb[i];

    // Wcat bf16: hi -> AB area (temporary), lo -> WLO (persistent).
    // Column permutation: smem row n <- output col o so thread (q,tc)
    // owns 4 contiguous outputs 16q+4tc..+3 in the epilogue.
    for (int i = tid; i < 128 * 32; i += THREADS) {
        int n = i >> 5, kp = (i & 31) * 2;
        int half = n >> 6;              // 0: W1, 1: W0-W1
        int nn = n & 63;
        int p = nn & 7, t = (nn >> 3) & 1;
        int o = (nn & 48) + ((p >> 1) << 2) + 2 * t + (p & 1);
        float v0, v1;
        if (half == 0) {
            v0 = w_stack[4096 + o * 64 + kp];
            v1 = w_stack[4096 + o * 64 + kp + 1];
        } else {
            v0 = w_stack[o * 64 + kp]     - w_stack[4096 + o * 64 + kp];
            v1 = w_stack[o * 64 + kp + 1] - w_stack[4096 + o * 64 + kp + 1];
        }
        uint32_t h = cvt2bf(v0, v1);
        float h0 = __uint_as_float(h << 16);
        float h1 = __uint_as_float(h & 0xffff0000u);
        uint32_t l = cvt2bf(v0 - h0, v1 - h1);
        int off = n * 128 + (((kp >> 3) ^ (n & 7)) << 4) + (kp & 7) * 2;
        *(uint32_t*)(smem + AB_OFF + off)  = h;
        *(uint32_t*)(smem + WLO_OFF + off) = l;
    }
    __syncthreads();

    // ---- B-hi fragments -> registers (kept for whole kernel) ----
    // nti 0,1 = h1 tiles (2q, 2q+1); nti 2,3 = hd tiles (2q+8, 2q+9)
    uint32_t Bh[4][4][2];
    #pragma unroll
    for (int nti = 0; nti < 4; nti++) {
        int nt = 2 * q + (nti & 1) + ((nti >> 1) << 3);
        #pragma unroll
        for (int k = 0; k < 4; k++) {
            int row  = nt * 8 + (lane & 7);
            int unit = k * 2 + ((lane >> 3) & 1);
            ldsm_x2(Bh[nti][k], sb + AB_OFF + row * 128 + ((unit ^ (row & 7)) << 4));
        }
    }
    __syncthreads();   // AB area now free for A tiles

    const int grp = lane >> 2, tc = lane & 3;
    const int o0  = 16 * q + 4 * tc;

    // B-lo ldsm addressing (per-k x4: 2 n-tiles x 2 k-halves)
    const int blrow1 = 16 * q + (lane & 7) + ((lane & 16) >> 1);   // h1 rows
    const int blrowd = blrow1 + 64;                                 // hd rows
    const int blun   = (lane >> 3) & 1;
    const uint32_t bl1base = sb + WLO_OFF + blrow1 * 128;
    const uint32_t bldbase = sb + WLO_OFF + blrowd * 128;

    // ---- prologue: stage first tile's x ----
    {
        const float4* src = (const float4*)x + (size_t)blockIdx.x * (TILE_M * 64 / 4);
        #pragma unroll
        for (int k = 0; k < 4; k++) {
            int j = tid + k * THREADS;
            cp_async16(sb + RAW_OFF + j * 16, src + j);
        }
    }
    CP_COMMIT();

    int buf = 0;
    for (int tile = blockIdx.x; tile < NTILES; tile += GRID)
    {
        // prefetch next tile into other raw buffer
        {
            int nt = tile + GRID;
            if (nt < NTILES) {
                const float4* src = (const float4*)x + (size_t)nt * (TILE_M * 64 / 4);
                uint32_t dst = sb + RAW_OFF + (buf ^ 1) * 16384;
                #pragma unroll
                for (int k = 0; k < 4; k++) {
                    int j = tid + k * THREADS;
                    cp_async16(dst + j * 16, src + j);
                }
            }
        }
        CP_COMMIT();
        CP_WAIT1();          // current tile's copy complete
        __syncthreads();     // + separates prev MMA reads from A rewrite

        // ---- convert: LDS raw -> gate partials + bf16 hi/lo STS ----
        {
            const float4* raw4 = (const float4*)(smem + RAW_OFF + buf * 16384);
            #pragma unroll
            for (int i = 0; i < 4; i++) {
                int j = tid + i * THREADS;
                int t = j >> 4, c = j & 15;
                float4 v = raw4[j];
                const float* ep = &emb_s[(t & 15) * 64 + c * 4];
                v.x += ep[0]; v.y += ep[1]; v.z += ep[2]; v.w += ep[3];
                const float* rp = &rwd_s[c * 4];
                float p = v.x * rp[0] + v.y * rp[1] + v.z * rp[2] + v.w * rp[3];
                p += __shfl_xor_sync(0xffffffffu, p, 1);
                p += __shfl_xor_sync(0xffffffffu, p, 2);
                p += __shfl_xor_sync(0xffffffffu, p, 4);
                p += __shfl_xor_sync(0xffffffffu, p, 8);
                if ((lane & 15) == 0) log_s[t] = p;
                uint32_t h0 = cvt2bf(v.x, v.y);
                uint32_t h1 = cvt2bf(v.z, v.w);
                float hx = __uint_as_float(h0 << 16), hy = __uint_as_float(h0 & 0xffff0000u);
                float hz = __uint_as_float(h1 << 16), hw = __uint_as_float(h1 & 0xffff0000u);
                uint32_t l0 = cvt2bf(v.x - hx, v.y - hy);
                uint32_t l1 = cvt2bf(v.z - hz, v.w - hw);
                int off = t * 128 + (((c >> 1) ^ (t & 7)) << 4) + (c & 1) * 8;
                *(uint2*)(smem + AB_OFF + off)        = make_uint2(h0, h1);
                *(uint2*)(smem + AB_OFF + off + 8192) = make_uint2(l0, l1);
            }
        }
        __syncthreads();

        // ---- MMA: xh·wh + xh·wl + xl·wh; B-hi regs, B-lo from SMEM ----
        float acc[2][4][4];
        #pragma unroll
        for (int m = 0; m < 2; m++)
            #pragma unroll
            for (int n = 0; n < 4; n++) {
                acc[m][n][0] = 0.f; acc[m][n][1] = 0.f;
                acc[m][n][2] = 0.f; acc[m][n][3] = 0.f;
            }

        #pragma unroll
        for (int k = 0; k < 4; k++) {
            uint32_t bl1[4], bld[4];
            {
                uint32_t u = (uint32_t)(k * 2 + blun);
                ldsm_x4(bl1, bl1base + ((u ^ (blrow1 & 7)) << 4));
                ldsm_x4(bld, bldbase + ((u ^ (blrowd & 7)) << 4));
            }
            #pragma unroll
            for (int m = 0; m < 2; m++) {
                int tok  = r * 32 + m * 16 + (lane & 15);
                int unit = k * 2 + (lane >> 4);
                uint32_t aaddr = sb + AB_OFF + tok * 128 + ((unit ^ (tok & 7)) << 4);
                uint32_t Ahi[4], Alo[4];
                ldsm_x4(Ahi, aaddr);
                ldsm_x4(Alo, aaddr + 8192);
                // pass 1: xh·wh
                mma_bf16(acc[m][0], Ahi, Bh[0][k]);
                mma_bf16(acc[m][1], Ahi, Bh[1][k]);
                mma_bf16(acc[m][2], Ahi, Bh[2][k]);
                mma_bf16(acc[m][3], Ahi, Bh[3][k]);
                // pass 2: xh·wl
                mma_bf16(acc[m][0], Ahi, &bl1[0]);
                mma_bf16(acc[m][1], Ahi, &bl1[2]);
                mma_bf16(acc[m][2], Ahi, &bld[0]);
                mma_bf16(acc[m][3], Ahi, &bld[2]);
                // pass 3: xl·wh
                mma_bf16(acc[m][0], Alo, Bh[0][k]);
                mma_bf16(acc[m][1], Alo, Bh[1][k]);
                mma_bf16(acc[m][2], Alo, Bh[2][k]);
                mma_bf16(acc[m][3], Alo, Bh[3][k]);
            }
        }

        // ---- epilogue: gate combine + STG.128 (permuted-contiguous cols) ----
        {
            float* outb = out + (size_t)tile * (TILE_M * 64);
            float4 b1v = *(const float4*)&b1_s[o0];
            float4 bdv = *(const float4*)&bd_s[o0];
            #pragma unroll
            for (int m = 0; m < 2; m++) {
                int t0 = r * 32 + m * 16 + grp;
                int t1 = t0 + 8;
                float a00 = 1.f / (1.f + __expf(-log_s[t0]));
                float a01 = 1.f / (1.f + __expf(-log_s[t1]));
                float4 w;
                w.x = fmaf(a00, acc[m][2][0] + bdv.x, acc[m][0][0] + b1v.x);
                w.y = fmaf(a00, acc[m][2][1] + bdv.y, acc[m][0][1] + b1v.y);
                w.z = fmaf(a00, acc[m][3][0] + bdv.z, acc[m][1][0] + b1v.z);
                w.w = fmaf(a00, acc[m][3][1] + bdv.w, acc[m][1][1] + b1v.w);
                *(float4*)&outb[t0 * 64 + o0] = w;
                w.x = fmaf(a01, acc[m][2][2] + bdv.x, acc[m][0][2] + b1v.x);
                w.y = fmaf(a01, acc[m][2][3] + bdv.y, acc[m][0][3] + b1v.y);
                w.z = fmaf(a01, acc[m][3][2] + bdv.z, acc[m][1][2] + b1v.z);
                w.w = fmaf(a01, acc[m][3][3] + bdv.w, acc[m][1][3] + b1v.w);
                *(float4*)&outb[t1 * 64 + o0] = w;
            }
        }
        buf ^= 1;
        // next iteration's top __syncthreads separates this epilogue/MMA
        // from the next convert's A-tile rewrite.
    }
}

extern "C" void kernel_launch(void* const* d_in, const int* in_sizes, int n_in,
                              void* d_out, int out_size)
{
    const float* x       = (const float*)d_in[0];
    const float* emb     = (const float*)d_in[1];
    const float* read_w  = (const float*)d_in[2];
    const float* w_stack = (const float*)d_in[3];
    const float* b_stack = (const float*)d_in[4];
    float* out = (float*)d_out;

    cudaFuncSetAttribute(sgl_mma6_kernel, cudaFuncAttributeMaxDynamicSharedMemorySize, SMEM_TOTAL);
    sgl_mma6_kernel<<<GRID, THREADS, SMEM_TOTAL>>>(x, emb, read_w, w_stack, b_stack, out);
}